// round 9
// baseline (speedup 1.0000x reference)
#include <cuda_runtime.h>

// Trilinear resample (B=4, D=64, H=64, W=64, C=32) fp32, identity theta.
// f = 62*i/63 => i0 = max(i-1,0), t(i) = 1 - i/63 (t=0 at i=0).
//
// R8 scheme + R9 change: each block loops over TWO consecutive d values
// (consecutive d share input z-plane d -> L1/L2 re-hit instead of a fresh
// DRAM-path round trip), with the 4-pg h-pair loop inside.
//
// Warp layout: lane = c4(0..7) + 8*j (j=0..3); column x = 3*seg + j.
// Per iter: lane serves rows h0=2p, h1=2p+1 (share middle y-row): 6 loads,
// two (y,z)-bilinears, g(x-1) via shfl_up(8), lanes j>=1 emit 2 outputs.

#define B_ 4
#define D_ 64
#define H_ 64
#define W_ 64
#define C4_ 8
#define SEGS_ 21

__global__ __launch_bounds__(256) void trilerp_hp_dloop_kernel(
    const float4* __restrict__ in, float4* __restrict__ out)
{
    const int lane = threadIdx.x & 31;
    const int wid  = threadIdx.x >> 5;       // 0..7
    const int c4 = lane & (C4_ - 1);
    const int j  = lane >> 3;                // 0..3

    const int seg = blockIdx.x;              // 0..20
    const int bdp = blockIdx.y;              // 0..127 : (b, d-pair)
    const int dp  = bdp & 31;                // d-pair index
    const int b   = bdp >> 5;
    const int x   = 3 * seg + j;             // 0..63

    const long rowY = (long)W_ * C4_;
    const long rowZ = (long)H_ * W_ * C4_;
    const long planeOut = (long)H_ * W_;

    for (int dd = 0; dd < 2; ++dd) {
        const int d = 2 * dp + dd;

        // z weights for this d
        const float fz = (float)d * (62.0f / 63.0f);
        const int z0 = max(d - 1, 0);
        const float tz = fz - (float)z0;
        const float sz = 1.0f - tz;

        const float4* pb = in + (((long)b * D_ + z0) * (long)H_ * W_ + x) * C4_ + c4;
        const long voxBase = (((long)b * D_ + d) * H_) * W_;

        #pragma unroll 2
        for (int pg = 0; pg < 4; ++pg) {
            const int p  = pg * 8 + wid;          // 0..31, warp-uniform
            const int h0 = 2 * p;

            float4 g0, g1;   // (y,z)-bilinear blends for rows h0, h1 at column x

            if (p == 0) {
                // h0=0 (ty0=0), h1=1 (ty1=62/63); y-rows {0,1}: 4 loads
                const float4 r0z0 = __ldg(pb);
                const float4 r1z0 = __ldg(pb + rowY);
                const float4 r0z1 = __ldg(pb + rowZ);
                const float4 r1z1 = __ldg(pb + rowZ + rowY);
                g0.x = fmaf(tz, r0z1.x, sz * r0z0.x);
                g0.y = fmaf(tz, r0z1.y, sz * r0z0.y);
                g0.z = fmaf(tz, r0z1.z, sz * r0z0.z);
                g0.w = fmaf(tz, r0z1.w, sz * r0z0.w);
                const float ty1 = 62.0f / 63.0f;
                const float sy1 = 1.0f - ty1;
                const float a = sy1 * sz, bw = ty1 * sz, c = sy1 * tz, e = ty1 * tz;
                g1.x = fmaf(e, r1z1.x, fmaf(c, r0z1.x, fmaf(bw, r1z0.x, a * r0z0.x)));
                g1.y = fmaf(e, r1z1.y, fmaf(c, r0z1.y, fmaf(bw, r1z0.y, a * r0z0.y)));
                g1.z = fmaf(e, r1z1.z, fmaf(c, r0z1.z, fmaf(bw, r1z0.z, a * r0z0.z)));
                g1.w = fmaf(e, r1z1.w, fmaf(c, r0z1.w, fmaf(bw, r1z0.w, a * r0z0.w)));
            } else {
                // rows 2p-1, 2p, 2p+1: 6 loads
                const float4* pr = pb + (long)(h0 - 1) * rowY;
                const float4 L0z0 = __ldg(pr);
                const float4 L1z0 = __ldg(pr + rowY);
                const float4 L2z0 = __ldg(pr + 2 * rowY);
                const float4 L0z1 = __ldg(pr + rowZ);
                const float4 L1z1 = __ldg(pr + rowZ + rowY);
                const float4 L2z1 = __ldg(pr + rowZ + 2 * rowY);

                const float ty0 = (float)(63 - 2 * p) * (1.0f / 63.0f);
                const float ty1 = (float)(62 - 2 * p) * (1.0f / 63.0f);
                const float sy0 = 1.0f - ty0;
                const float sy1 = 1.0f - ty1;

                const float a0 = sy0 * sz, b0w = ty0 * sz, c0 = sy0 * tz, e0 = ty0 * tz;
                g0.x = fmaf(e0, L1z1.x, fmaf(c0, L0z1.x, fmaf(b0w, L1z0.x, a0 * L0z0.x)));
                g0.y = fmaf(e0, L1z1.y, fmaf(c0, L0z1.y, fmaf(b0w, L1z0.y, a0 * L0z0.y)));
                g0.z = fmaf(e0, L1z1.z, fmaf(c0, L0z1.z, fmaf(b0w, L1z0.z, a0 * L0z0.z)));
                g0.w = fmaf(e0, L1z1.w, fmaf(c0, L0z1.w, fmaf(b0w, L1z0.w, a0 * L0z0.w)));

                const float a1 = sy1 * sz, b1w = ty1 * sz, c1 = sy1 * tz, e1 = ty1 * tz;
                g1.x = fmaf(e1, L2z1.x, fmaf(c1, L1z1.x, fmaf(b1w, L2z0.x, a1 * L1z0.x)));
                g1.y = fmaf(e1, L2z1.y, fmaf(c1, L1z1.y, fmaf(b1w, L2z0.y, a1 * L1z0.y)));
                g1.z = fmaf(e1, L2z1.z, fmaf(c1, L1z1.z, fmaf(b1w, L2z0.z, a1 * L1z0.z)));
                g1.w = fmaf(e1, L2z1.w, fmaf(c1, L1z1.w, fmaf(b1w, L2z0.w, a1 * L1z0.w)));
            }

            // g(x-1) from lane-8 (previous column, same c4)
            float4 gp0, gp1;
            gp0.x = __shfl_up_sync(0xFFFFFFFFu, g0.x, 8);
            gp0.y = __shfl_up_sync(0xFFFFFFFFu, g0.y, 8);
            gp0.z = __shfl_up_sync(0xFFFFFFFFu, g0.z, 8);
            gp0.w = __shfl_up_sync(0xFFFFFFFFu, g0.w, 8);
            gp1.x = __shfl_up_sync(0xFFFFFFFFu, g1.x, 8);
            gp1.y = __shfl_up_sync(0xFFFFFFFFu, g1.y, 8);
            gp1.z = __shfl_up_sync(0xFFFFFFFFu, g1.z, 8);
            gp1.w = __shfl_up_sync(0xFFFFFFFFu, g1.w, 8);

            const long voxRow0 = voxBase + (long)h0 * W_;
            const long voxRow1 = voxRow0 + W_;

            if (j > 0) {
                const float t = 1.0f - (float)x * (1.0f / 63.0f);  // x >= 1 here
                const float s = 1.0f - t;
                float4 r0, r1;
                r0.x = fmaf(t, g0.x, s * gp0.x);
                r0.y = fmaf(t, g0.y, s * gp0.y);
                r0.z = fmaf(t, g0.z, s * gp0.z);
                r0.w = fmaf(t, g0.w, s * gp0.w);
                r1.x = fmaf(t, g1.x, s * gp1.x);
                r1.y = fmaf(t, g1.y, s * gp1.y);
                r1.z = fmaf(t, g1.z, s * gp1.z);
                r1.w = fmaf(t, g1.w, s * gp1.w);
                out[(voxRow0 + x) * C4_ + c4] = r0;
                out[(voxRow1 + x) * C4_ + c4] = r1;
            } else if (seg == 0) {
                // x = 0: t = 0 -> out = g(0)
                out[voxRow0 * C4_ + c4] = g0;
                out[voxRow1 * C4_ + c4] = g1;
            }
        }
    }
}

extern "C" void kernel_launch(void* const* d_in, const int* in_sizes, int n_in,
                              void* d_out, int out_size)
{
    const float4* in = (const float4*)d_in[0];
    float4* out = (float4*)d_out;
    dim3 grid(SEGS_, B_ * (D_ / 2), 1);   // (21, 128) -> 2688 blocks
    trilerp_hp_dloop_kernel<<<grid, 256>>>(in, out);
}

// round 10
// speedup vs baseline: 1.0430x; 1.0430x over previous
#include <cuda_runtime.h>

// Trilinear resample (B=4, D=64, H=64, W=64, C=32) fp32, identity theta.
// f = 62*i/63 => i0 = max(i-1,0), t(i) = 1 - i/63 (t=0 at i=0).
//
// R8 scheme (best: 47.5us) + R10 change: __launch_bounds__(256, 8) to force
// regs<=32 -> 8 blocks/SM (64 warps) for more memory-level concurrency.
//
// Warp layout: lane = c4(0..7) + 8*j (j=0..3); column x = 3*seg + j.
// Block loops over 4 pg groups (unroll 2). Per iter: lane serves rows
// h0=2p, h1=2p+1 (share middle y-row): 6 loads, two (y,z)-bilinears,
// g(x-1) via shfl_up(8), lanes j>=1 emit 2 outputs.

#define B_ 4
#define D_ 64
#define H_ 64
#define W_ 64
#define C4_ 8
#define SEGS_ 21

__global__ __launch_bounds__(256, 8) void trilerp_hp_occ_kernel(
    const float4* __restrict__ in, float4* __restrict__ out)
{
    const int lane = threadIdx.x & 31;
    const int wid  = threadIdx.x >> 5;       // 0..7
    const int c4 = lane & (C4_ - 1);
    const int j  = lane >> 3;                // 0..3

    const int seg = blockIdx.x;              // 0..20
    const int bd  = blockIdx.y;              // 0..255
    const int d   = bd & (D_ - 1);
    const int b   = bd >> 6;
    const int x   = 3 * seg + j;             // 0..63

    // x-lerp weights (fixed per thread)
    const float t = (x == 0) ? 0.0f : (1.0f - (float)x * (1.0f / 63.0f));
    const float s = 1.0f - t;

    // z weights (fixed per block)
    const float fz = (float)d * (62.0f / 63.0f);
    const int z0 = max(d - 1, 0);
    const float tz = fz - (float)z0;
    const float sz = 1.0f - tz;

    const long rowY = (long)W_ * C4_;
    const long rowZ = (long)H_ * W_ * C4_;
    const float4* pb = in + (((long)b * D_ + z0) * (long)H_ * W_ + x) * C4_ + c4;

    const long voxBase = (((long)b * D_ + d) * H_) * W_;

    #pragma unroll 2
    for (int pg = 0; pg < 4; ++pg) {
        const int p  = pg * 8 + wid;          // 0..31, warp-uniform
        const int h0 = 2 * p;

        float4 g0, g1;   // (y,z)-bilinear blends for rows h0, h1 at column x

        if (p == 0) {
            // h0=0 (ty0=0), h1=1 (ty1=62/63); both use y-rows {0,1}: 4 loads
            const float4 r0z0 = __ldg(pb);
            const float4 r1z0 = __ldg(pb + rowY);
            const float4 r0z1 = __ldg(pb + rowZ);
            const float4 r1z1 = __ldg(pb + rowZ + rowY);
            g0.x = fmaf(tz, r0z1.x, sz * r0z0.x);
            g0.y = fmaf(tz, r0z1.y, sz * r0z0.y);
            g0.z = fmaf(tz, r0z1.z, sz * r0z0.z);
            g0.w = fmaf(tz, r0z1.w, sz * r0z0.w);
            const float ty1 = 62.0f / 63.0f;
            const float sy1 = 1.0f - ty1;
            const float a = sy1 * sz, bw = ty1 * sz, c = sy1 * tz, e = ty1 * tz;
            g1.x = fmaf(e, r1z1.x, fmaf(c, r0z1.x, fmaf(bw, r1z0.x, a * r0z0.x)));
            g1.y = fmaf(e, r1z1.y, fmaf(c, r0z1.y, fmaf(bw, r1z0.y, a * r0z0.y)));
            g1.z = fmaf(e, r1z1.z, fmaf(c, r0z1.z, fmaf(bw, r1z0.z, a * r0z0.z)));
            g1.w = fmaf(e, r1z1.w, fmaf(c, r0z1.w, fmaf(bw, r1z0.w, a * r0z0.w)));
        } else {
            // rows 2p-1, 2p, 2p+1; g0 uses (2p-1,2p), g1 uses (2p,2p+1): 6 loads
            const float4* pr = pb + (long)(h0 - 1) * rowY;
            const float4 L0z0 = __ldg(pr);
            const float4 L1z0 = __ldg(pr + rowY);
            const float4 L2z0 = __ldg(pr + 2 * rowY);
            const float4 L0z1 = __ldg(pr + rowZ);
            const float4 L1z1 = __ldg(pr + rowZ + rowY);
            const float4 L2z1 = __ldg(pr + rowZ + 2 * rowY);

            const float ty0 = (float)(63 - 2 * p) * (1.0f / 63.0f);
            const float ty1 = (float)(62 - 2 * p) * (1.0f / 63.0f);
            const float sy0 = 1.0f - ty0;
            const float sy1 = 1.0f - ty1;

            const float a0 = sy0 * sz, b0w = ty0 * sz, c0 = sy0 * tz, e0 = ty0 * tz;
            g0.x = fmaf(e0, L1z1.x, fmaf(c0, L0z1.x, fmaf(b0w, L1z0.x, a0 * L0z0.x)));
            g0.y = fmaf(e0, L1z1.y, fmaf(c0, L0z1.y, fmaf(b0w, L1z0.y, a0 * L0z0.y)));
            g0.z = fmaf(e0, L1z1.z, fmaf(c0, L0z1.z, fmaf(b0w, L1z0.z, a0 * L0z0.z)));
            g0.w = fmaf(e0, L1z1.w, fmaf(c0, L0z1.w, fmaf(b0w, L1z0.w, a0 * L0z0.w)));

            const float a1 = sy1 * sz, b1w = ty1 * sz, c1 = sy1 * tz, e1 = ty1 * tz;
            g1.x = fmaf(e1, L2z1.x, fmaf(c1, L1z1.x, fmaf(b1w, L2z0.x, a1 * L1z0.x)));
            g1.y = fmaf(e1, L2z1.y, fmaf(c1, L1z1.y, fmaf(b1w, L2z0.y, a1 * L1z0.y)));
            g1.z = fmaf(e1, L2z1.z, fmaf(c1, L1z1.z, fmaf(b1w, L2z0.z, a1 * L1z0.z)));
            g1.w = fmaf(e1, L2z1.w, fmaf(c1, L1z1.w, fmaf(b1w, L2z0.w, a1 * L1z0.w)));
        }

        // g(x-1) from lane-8 (previous column, same c4)
        float4 gp0, gp1;
        gp0.x = __shfl_up_sync(0xFFFFFFFFu, g0.x, 8);
        gp0.y = __shfl_up_sync(0xFFFFFFFFu, g0.y, 8);
        gp0.z = __shfl_up_sync(0xFFFFFFFFu, g0.z, 8);
        gp0.w = __shfl_up_sync(0xFFFFFFFFu, g0.w, 8);
        gp1.x = __shfl_up_sync(0xFFFFFFFFu, g1.x, 8);
        gp1.y = __shfl_up_sync(0xFFFFFFFFu, g1.y, 8);
        gp1.z = __shfl_up_sync(0xFFFFFFFFu, g1.z, 8);
        gp1.w = __shfl_up_sync(0xFFFFFFFFu, g1.w, 8);

        const long voxRow0 = voxBase + (long)h0 * W_;
        const long voxRow1 = voxRow0 + W_;

        if (j > 0) {
            float4 r0, r1;
            r0.x = fmaf(t, g0.x, s * gp0.x);
            r0.y = fmaf(t, g0.y, s * gp0.y);
            r0.z = fmaf(t, g0.z, s * gp0.z);
            r0.w = fmaf(t, g0.w, s * gp0.w);
            r1.x = fmaf(t, g1.x, s * gp1.x);
            r1.y = fmaf(t, g1.y, s * gp1.y);
            r1.z = fmaf(t, g1.z, s * gp1.z);
            r1.w = fmaf(t, g1.w, s * gp1.w);
            out[(voxRow0 + x) * C4_ + c4] = r0;
            out[(voxRow1 + x) * C4_ + c4] = r1;
        } else if (seg == 0) {
            // x = 0: t = 0 -> out = g(0)
            out[voxRow0 * C4_ + c4] = g0;
            out[voxRow1 * C4_ + c4] = g1;
        }
    }
}

extern "C" void kernel_launch(void* const* d_in, const int* in_sizes, int n_in,
                              void* d_out, int out_size)
{
    const float4* in = (const float4*)d_in[0];
    float4* out = (float4*)d_out;
    dim3 grid(SEGS_, B_ * D_, 1);   // (21, 256) -> 5376 blocks
    trilerp_hp_occ_kernel<<<grid, 256>>>(in, out);
}

// round 11
// speedup vs baseline: 1.0442x; 1.0012x over previous
#include <cuda_runtime.h>

// Trilinear resample (B=4, D=64, H=64, W=64, C=32) fp32, identity theta.
// f = 62*i/63 => y0 = h-1 (h>=1), ty(h) = (63-h)/63; ty(0)=0.
//
// Quad-row warp-shuffle kernel: lane = c4(0..7) + 8*j (j=0..3), column
// x = 3*seg + j. Each lane serves FOUR output rows h = 4p..4p+3:
//   - load 5 y-rows (4p-1..4p+3, clamped) x 2 z-planes = 10 float4 (high MLP)
//   - z-lerp the 5 rows, then 4 y-lerps -> g(h, x)
//   - g(h, x-1) via shfl_up(8); lanes j>=1 emit 4 outputs
// Read lines per output line: 3.33 (vs 4.0 in the h-pair version).

#define B_ 4
#define D_ 64
#define H_ 64
#define W_ 64
#define C4_ 8
#define SEGS_ 21

__global__ __launch_bounds__(256) void trilerp_quad_kernel(
    const float4* __restrict__ in, float4* __restrict__ out)
{
    const int lane = threadIdx.x & 31;
    const int wid  = threadIdx.x >> 5;        // 0..7
    const int c4 = lane & (C4_ - 1);
    const int j  = lane >> 3;                 // 0..3

    const int seg = blockIdx.x;               // 0..20
    const int by  = blockIdx.y;               // 0..511 : (b, d, pgHalf)
    const int pgh = by & 1;                   // 0..1
    const int d   = (by >> 1) & (D_ - 1);
    const int b   = by >> 7;
    const int p   = pgh * 8 + wid;            // 0..15 (quad index), warp-uniform
    const int h0  = 4 * p;
    const int x   = 3 * seg + j;              // 0..63

    // x-lerp weights (fixed per thread)
    const float t = (x == 0) ? 0.0f : (1.0f - (float)x * (1.0f / 63.0f));
    const float s = 1.0f - t;

    // z weights
    const float fz = (float)d * (62.0f / 63.0f);
    const int z0 = max(d - 1, 0);
    const float tz = fz - (float)z0;
    const float sz = 1.0f - tz;

    const long rowY = (long)W_ * C4_;
    const long rowZ = (long)H_ * W_ * C4_;
    const float4* pb = in + (((long)b * D_ + z0) * (long)H_ * W_ + x) * C4_ + c4;

    // 5 row indices (clamped at 0 for p==0); warp-uniform
    long off0 = (long)max(h0 - 1, 0) * rowY;
    long off1 = (long)(h0 + 0) * rowY;
    long off2 = (long)(h0 + 1) * rowY;
    long off3 = (long)(h0 + 2) * rowY;
    long off4 = (long)(h0 + 3) * rowY;

    // 10 independent loads
    const float4 A0 = __ldg(pb + off0);
    const float4 A1 = __ldg(pb + off1);
    const float4 A2 = __ldg(pb + off2);
    const float4 A3 = __ldg(pb + off3);
    const float4 A4 = __ldg(pb + off4);
    const float4 B0 = __ldg(pb + off0 + rowZ);
    const float4 B1 = __ldg(pb + off1 + rowZ);
    const float4 B2 = __ldg(pb + off2 + rowZ);
    const float4 B3 = __ldg(pb + off3 + rowZ);
    const float4 B4 = __ldg(pb + off4 + rowZ);

    // z-lerp the 5 rows
    float4 R0, R1, R2, R3, R4;
    R0.x = fmaf(tz, B0.x, sz * A0.x); R0.y = fmaf(tz, B0.y, sz * A0.y);
    R0.z = fmaf(tz, B0.z, sz * A0.z); R0.w = fmaf(tz, B0.w, sz * A0.w);
    R1.x = fmaf(tz, B1.x, sz * A1.x); R1.y = fmaf(tz, B1.y, sz * A1.y);
    R1.z = fmaf(tz, B1.z, sz * A1.z); R1.w = fmaf(tz, B1.w, sz * A1.w);
    R2.x = fmaf(tz, B2.x, sz * A2.x); R2.y = fmaf(tz, B2.y, sz * A2.y);
    R2.z = fmaf(tz, B2.z, sz * A2.z); R2.w = fmaf(tz, B2.w, sz * A2.w);
    R3.x = fmaf(tz, B3.x, sz * A3.x); R3.y = fmaf(tz, B3.y, sz * A3.y);
    R3.z = fmaf(tz, B3.z, sz * A3.z); R3.w = fmaf(tz, B3.w, sz * A3.w);
    R4.x = fmaf(tz, B4.x, sz * A4.x); R4.y = fmaf(tz, B4.y, sz * A4.y);
    R4.z = fmaf(tz, B4.z, sz * A4.z); R4.w = fmaf(tz, B4.w, sz * A4.w);

    // y-lerps: g_k for rows h = h0+k, k = 0..3
    // ty(h) = (63-h)/63 for h>=1; ty(0) = 0 (p==0, k==0 case)
    const float ty0 = (p == 0) ? 0.0f : (float)(63 - h0) * (1.0f / 63.0f);
    const float ty1 = (float)(62 - h0) * (1.0f / 63.0f);
    const float ty2 = (float)(61 - h0) * (1.0f / 63.0f);
    const float ty3 = (float)(60 - h0) * (1.0f / 63.0f);

    float4 g0, g1, g2, g3;
    #define YLERP(G, RA, RB, TY) \
        G.x = fmaf(TY, RB.x, (1.0f - TY) * RA.x); \
        G.y = fmaf(TY, RB.y, (1.0f - TY) * RA.y); \
        G.z = fmaf(TY, RB.z, (1.0f - TY) * RA.z); \
        G.w = fmaf(TY, RB.w, (1.0f - TY) * RA.w);
    YLERP(g0, R0, R1, ty0)
    YLERP(g1, R1, R2, ty1)
    YLERP(g2, R2, R3, ty2)
    YLERP(g3, R3, R4, ty3)
    #undef YLERP

    // g(x-1) from lane-8 (previous column, same c4)
    float4 q0, q1, q2, q3;
    #define SH(Q, G) \
        Q.x = __shfl_up_sync(0xFFFFFFFFu, G.x, 8); \
        Q.y = __shfl_up_sync(0xFFFFFFFFu, G.y, 8); \
        Q.z = __shfl_up_sync(0xFFFFFFFFu, G.z, 8); \
        Q.w = __shfl_up_sync(0xFFFFFFFFu, G.w, 8);
    SH(q0, g0) SH(q1, g1) SH(q2, g2) SH(q3, g3)
    #undef SH

    const long voxRow = (((long)b * D_ + d) * H_ + h0) * W_;   // row h0
    const long rowOutStride = (long)W_ * C4_;
    float4* po = out + voxRow * C4_ + (long)x * C4_ + c4;

    if (j > 0) {
        float4 r;
        #define XLERP_ST(G, Q, K) \
            r.x = fmaf(t, G.x, s * Q.x); \
            r.y = fmaf(t, G.y, s * Q.y); \
            r.z = fmaf(t, G.z, s * Q.z); \
            r.w = fmaf(t, G.w, s * Q.w); \
            po[(long)(K) * rowOutStride] = r;
        XLERP_ST(g0, q0, 0)
        XLERP_ST(g1, q1, 1)
        XLERP_ST(g2, q2, 2)
        XLERP_ST(g3, q3, 3)
        #undef XLERP_ST
    } else if (seg == 0) {
        // x = 0: t = 0 -> out = g(0)
        po[0] = g0;
        po[rowOutStride] = g1;
        po[2 * rowOutStride] = g2;
        po[3 * rowOutStride] = g3;
    }
}

extern "C" void kernel_launch(void* const* d_in, const int* in_sizes, int n_in,
                              void* d_out, int out_size)
{
    const float4* in = (const float4*)d_in[0];
    float4* out = (float4*)d_out;
    dim3 grid(SEGS_, B_ * D_ * 2, 1);   // (21, 512) -> 10752 blocks
    trilerp_quad_kernel<<<grid, 256>>>(in, out);
}

// round 12
// speedup vs baseline: 1.0662x; 1.0210x over previous
#include <cuda_runtime.h>

// Trilinear resample (B=4, D=64, H=64, W=64, C=32) fp32, identity theta.
// f = 62*i/63 => i0 = max(i-1,0), t(i) = 1 - i/63 (t=0 at i=0).
//
// Champion (R8) scheme: warp-shuffle h-pair kernel, block loops over the 4
// pg groups for one (b,d) (unroll 2 -> two independent 6-load chains per
// warp). Micro-cleanups only: x-lerp weights hoisted out of the pg loop.
//
// Warp layout: lane = c4(0..7) + 8*j (j=0..3); column x = 3*seg + j.
// Per iter: lane serves rows h0=2p, h1=2p+1 (share middle y-row): 6 loads,
// two (y,z)-bilinears, g(x-1) via shfl_up(8), lanes j>=1 emit 2 outputs.

#define B_ 4
#define D_ 64
#define H_ 64
#define W_ 64
#define C4_ 8
#define SEGS_ 21

__global__ __launch_bounds__(256) void trilerp_final_kernel(
    const float4* __restrict__ in, float4* __restrict__ out)
{
    const int lane = threadIdx.x & 31;
    const int wid  = threadIdx.x >> 5;       // 0..7
    const int c4 = lane & (C4_ - 1);
    const int j  = lane >> 3;                // 0..3

    const int seg = blockIdx.x;              // 0..20
    const int bd  = blockIdx.y;              // 0..255
    const int d   = bd & (D_ - 1);
    const int b   = bd >> 6;
    const int x   = 3 * seg + j;             // 0..63

    // x-lerp weights (fixed per thread; t=0 only at x=0 which is j==0/seg==0)
    const float t = (x == 0) ? 0.0f : (1.0f - (float)x * (1.0f / 63.0f));
    const float s = 1.0f - t;

    // z weights (fixed per block)
    const float fz = (float)d * (62.0f / 63.0f);
    const int z0 = max(d - 1, 0);
    const float tz = fz - (float)z0;
    const float sz = 1.0f - tz;

    const long rowY = (long)W_ * C4_;
    const long rowZ = (long)H_ * W_ * C4_;
    const float4* pb = in + (((long)b * D_ + z0) * (long)H_ * W_ + x) * C4_ + c4;

    const long voxBase = (((long)b * D_ + d) * H_) * W_;  // row h -> voxBase + h*W_

    #pragma unroll 2
    for (int pg = 0; pg < 4; ++pg) {
        const int p  = pg * 8 + wid;          // 0..31, warp-uniform
        const int h0 = 2 * p;

        float4 g0, g1;   // (y,z)-bilinear blends for rows h0, h1 at column x

        if (p == 0) {
            // h0=0 (ty0=0), h1=1 (ty1=62/63); both use y-rows {0,1}: 4 loads
            const float4 r0z0 = __ldg(pb);
            const float4 r1z0 = __ldg(pb + rowY);
            const float4 r0z1 = __ldg(pb + rowZ);
            const float4 r1z1 = __ldg(pb + rowZ + rowY);
            g0.x = fmaf(tz, r0z1.x, sz * r0z0.x);
            g0.y = fmaf(tz, r0z1.y, sz * r0z0.y);
            g0.z = fmaf(tz, r0z1.z, sz * r0z0.z);
            g0.w = fmaf(tz, r0z1.w, sz * r0z0.w);
            const float ty1 = 62.0f / 63.0f;
            const float sy1 = 1.0f - ty1;
            const float a = sy1 * sz, bw = ty1 * sz, c = sy1 * tz, e = ty1 * tz;
            g1.x = fmaf(e, r1z1.x, fmaf(c, r0z1.x, fmaf(bw, r1z0.x, a * r0z0.x)));
            g1.y = fmaf(e, r1z1.y, fmaf(c, r0z1.y, fmaf(bw, r1z0.y, a * r0z0.y)));
            g1.z = fmaf(e, r1z1.z, fmaf(c, r0z1.z, fmaf(bw, r1z0.z, a * r0z0.z)));
            g1.w = fmaf(e, r1z1.w, fmaf(c, r0z1.w, fmaf(bw, r1z0.w, a * r0z0.w)));
        } else {
            // rows 2p-1, 2p, 2p+1; g0 uses (2p-1,2p), g1 uses (2p,2p+1): 6 loads
            const float4* pr = pb + (long)(h0 - 1) * rowY;
            const float4 L0z0 = __ldg(pr);
            const float4 L1z0 = __ldg(pr + rowY);
            const float4 L2z0 = __ldg(pr + 2 * rowY);
            const float4 L0z1 = __ldg(pr + rowZ);
            const float4 L1z1 = __ldg(pr + rowZ + rowY);
            const float4 L2z1 = __ldg(pr + rowZ + 2 * rowY);

            const float ty0 = (float)(63 - 2 * p) * (1.0f / 63.0f);
            const float ty1 = (float)(62 - 2 * p) * (1.0f / 63.0f);
            const float sy0 = 1.0f - ty0;
            const float sy1 = 1.0f - ty1;

            const float a0 = sy0 * sz, b0w = ty0 * sz, c0 = sy0 * tz, e0 = ty0 * tz;
            g0.x = fmaf(e0, L1z1.x, fmaf(c0, L0z1.x, fmaf(b0w, L1z0.x, a0 * L0z0.x)));
            g0.y = fmaf(e0, L1z1.y, fmaf(c0, L0z1.y, fmaf(b0w, L1z0.y, a0 * L0z0.y)));
            g0.z = fmaf(e0, L1z1.z, fmaf(c0, L0z1.z, fmaf(b0w, L1z0.z, a0 * L0z0.z)));
            g0.w = fmaf(e0, L1z1.w, fmaf(c0, L0z1.w, fmaf(b0w, L1z0.w, a0 * L0z0.w)));

            const float a1 = sy1 * sz, b1w = ty1 * sz, c1 = sy1 * tz, e1 = ty1 * tz;
            g1.x = fmaf(e1, L2z1.x, fmaf(c1, L1z1.x, fmaf(b1w, L2z0.x, a1 * L1z0.x)));
            g1.y = fmaf(e1, L2z1.y, fmaf(c1, L1z1.y, fmaf(b1w, L2z0.y, a1 * L1z0.y)));
            g1.z = fmaf(e1, L2z1.z, fmaf(c1, L1z1.z, fmaf(b1w, L2z0.z, a1 * L1z0.z)));
            g1.w = fmaf(e1, L2z1.w, fmaf(c1, L1z1.w, fmaf(b1w, L2z0.w, a1 * L1z0.w)));
        }

        // g(x-1) from lane-8 (previous column, same c4)
        float4 gp0, gp1;
        gp0.x = __shfl_up_sync(0xFFFFFFFFu, g0.x, 8);
        gp0.y = __shfl_up_sync(0xFFFFFFFFu, g0.y, 8);
        gp0.z = __shfl_up_sync(0xFFFFFFFFu, g0.z, 8);
        gp0.w = __shfl_up_sync(0xFFFFFFFFu, g0.w, 8);
        gp1.x = __shfl_up_sync(0xFFFFFFFFu, g1.x, 8);
        gp1.y = __shfl_up_sync(0xFFFFFFFFu, g1.y, 8);
        gp1.z = __shfl_up_sync(0xFFFFFFFFu, g1.z, 8);
        gp1.w = __shfl_up_sync(0xFFFFFFFFu, g1.w, 8);

        const long voxRow0 = voxBase + (long)h0 * W_;
        const long voxRow1 = voxRow0 + W_;

        if (j > 0) {
            float4 r0, r1;
            r0.x = fmaf(t, g0.x, s * gp0.x);
            r0.y = fmaf(t, g0.y, s * gp0.y);
            r0.z = fmaf(t, g0.z, s * gp0.z);
            r0.w = fmaf(t, g0.w, s * gp0.w);
            r1.x = fmaf(t, g1.x, s * gp1.x);
            r1.y = fmaf(t, g1.y, s * gp1.y);
            r1.z = fmaf(t, g1.z, s * gp1.z);
            r1.w = fmaf(t, g1.w, s * gp1.w);
            out[(voxRow0 + x) * C4_ + c4] = r0;
            out[(voxRow1 + x) * C4_ + c4] = r1;
        } else if (seg == 0) {
            // x = 0: t = 0 -> out = g(0)
            out[voxRow0 * C4_ + c4] = g0;
            out[voxRow1 * C4_ + c4] = g1;
        }
    }
}

extern "C" void kernel_launch(void* const* d_in, const int* in_sizes, int n_in,
                              void* d_out, int out_size)
{
    const float4* in = (const float4*)d_in[0];
    float4* out = (float4*)d_out;
    dim3 grid(SEGS_, B_ * D_, 1);   // (21, 256) -> 5376 blocks
    trilerp_final_kernel<<<grid, 256>>>(in, out);
}